// round 7
// baseline (speedup 1.0000x reference)
#include <cuda_runtime.h>
#include <cuda_bf16.h>
#include <math.h>

// Problem constants (shapes fixed by the reference setup)
#define NMAX   40000
#define EMAX   400000
#define EPRIME (EMAX + NMAX)

// ---------------- device scratch (no allocation allowed) ----------------
__device__ float g_bufA[NMAX * 256];
__device__ float g_bufB[NMAX * 256];
__device__ float g_als[NMAX];
__device__ float g_ald[NMAX];
__device__ float g_escr[EPRIME];      // per-edge e / exp(e-m) scratch (sorted order)
__device__ int   g_deg[NMAX];
__device__ int   g_rowptr[NMAX + 1];
__device__ int   g_cursor[NMAX + 1];
__device__ int   g_srcs[EPRIME];      // src node of each dst-sorted edge
__device__ int   g_is64;

// edge_index may arrive as int64 (reference declares int64) or int32 (default
// JAX x64-disabled). Detected at runtime.
__device__ __forceinline__ int edge_at(const void* p, long long idx) {
  if (g_is64) return (int)((const long long*)p)[idx];
  return ((const int*)p)[idx];
}

// ---------------- CSR build ----------------
__global__ void detect_zero_kernel(const void* __restrict__ eidx) {
  int t = blockIdx.x * blockDim.x + threadIdx.x;
  if (t == 0) {
    // If the buffer is int64 little-endian with values < 2^31, every odd
    // int32 word is zero. Random int32 node ids make that impossible.
    const int* p = (const int*)eidx;
    int is64 = 1;
    for (int i = 0; i < 64; ++i) {
      if (p[2 * i + 1] != 0) { is64 = 0; break; }
    }
    g_is64 = is64;
  }
  for (int i = t; i < NMAX; i += gridDim.x * blockDim.x) g_deg[i] = 0;
}

__global__ void hist_kernel(const void* __restrict__ eidx, int E) {
  int t = blockIdx.x * blockDim.x + threadIdx.x;
  if (t >= E) return;
  int d = edge_at(eidx, (long long)E + t);
  atomicAdd(&g_deg[d], 1);
}

__global__ void scan_kernel(int N) {
  const int T = 1024;
  int t = threadIdx.x;
  int per = (N + T - 1) / T;
  int lo = t * per;
  int hi = min(lo + per, N);
  int s = 0;
  for (int i = lo; i < hi; ++i) s += g_deg[i] + 1;  // +1 self loop
  __shared__ int sh[T];
  sh[t] = s;
  __syncthreads();
  for (int off = 1; off < T; off <<= 1) {
    int v = (t >= off) ? sh[t - off] : 0;
    __syncthreads();
    sh[t] += v;
    __syncthreads();
  }
  int run = (t == 0) ? 0 : sh[t - 1];
  for (int i = lo; i < hi; ++i) {
    g_rowptr[i] = run;
    g_cursor[i] = run;
    run += g_deg[i] + 1;
  }
  if (hi == N) { g_rowptr[N] = run; g_cursor[N] = run; }
}

__global__ void scatter_kernel(const void* __restrict__ eidx, int E, int N) {
  int t = blockIdx.x * blockDim.x + threadIdx.x;
  if (t < E) {
    int s = edge_at(eidx, t);
    int d = edge_at(eidx, (long long)E + t);
    int pos = atomicAdd(&g_cursor[d], 1);
    g_srcs[pos] = s;
  } else if (t < E + N) {
    int nd = t - E;                     // self loop
    int pos = atomicAdd(&g_cursor[nd], 1);
    g_srcs[pos] = nd;
  }
}

// ---------------- fp32 SIMT GEMM: C[N,M] = A[N,K] * W[K,M] ----------------
// 128x128 tile, BK=16, 256 threads, 8x8 per thread (split 4+4).
__global__ __launch_bounds__(256) void gemm_kernel(const float* __restrict__ A,
                                                   const float* __restrict__ W,
                                                   float* __restrict__ C,
                                                   int N, int K, int M) {
  __shared__ float As[16][132];   // padded: conflict-light transposed stores, 16B-aligned rows
  __shared__ float Bs[16][128];
  const int bm = blockIdx.y * 128;
  const int bn = blockIdx.x * 128;
  const int tid = threadIdx.x;
  const int tr = tid >> 4;        // 0..15
  const int tc = tid & 15;        // 0..15
  const int ar = tid >> 2;        // 0..63 (A-load row)
  const int ac = tid & 3;         // 0..3  (A-load k-chunk)
  const int br = tid >> 5;        // 0..7  (B-load k-row)
  const int bc = tid & 31;        // 0..31 (B-load col-chunk)

  float acc[8][8];
#pragma unroll
  for (int i = 0; i < 8; ++i)
#pragma unroll
    for (int j = 0; j < 8; ++j) acc[i][j] = 0.f;

  for (int k0 = 0; k0 < K; k0 += 16) {
#pragma unroll
    for (int h = 0; h < 2; ++h) {
      int row = bm + ar + h * 64;
      float4 v = make_float4(0.f, 0.f, 0.f, 0.f);
      if (row < N) v = *(const float4*)(A + (size_t)row * K + k0 + ac * 4);
      As[ac * 4 + 0][ar + h * 64] = v.x;
      As[ac * 4 + 1][ar + h * 64] = v.y;
      As[ac * 4 + 2][ar + h * 64] = v.z;
      As[ac * 4 + 3][ar + h * 64] = v.w;
    }
#pragma unroll
    for (int h = 0; h < 2; ++h) {
      int krow = k0 + br + h * 8;
      float4 v = *(const float4*)(W + (size_t)krow * M + bn + bc * 4);
      *(float4*)&Bs[br + h * 8][bc * 4] = v;
    }
    __syncthreads();
#pragma unroll
    for (int kk = 0; kk < 16; ++kk) {
      float a[8], b[8];
      *(float4*)&a[0] = *(const float4*)&As[kk][tr * 4];
      *(float4*)&a[4] = *(const float4*)&As[kk][64 + tr * 4];
      *(float4*)&b[0] = *(const float4*)&Bs[kk][tc * 4];
      *(float4*)&b[4] = *(const float4*)&Bs[kk][64 + tc * 4];
#pragma unroll
      for (int i = 0; i < 8; ++i)
#pragma unroll
        for (int j = 0; j < 8; ++j) acc[i][j] = fmaf(a[i], b[j], acc[i][j]);
    }
    __syncthreads();
  }

#pragma unroll
  for (int i = 0; i < 8; ++i) {
    int row = bm + ((i < 4) ? (tr * 4 + i) : (64 + tr * 4 + (i - 4)));
    if (row >= N) continue;
    float* crow = C + (size_t)row * M + bn;
    *(float4*)(crow + tc * 4) =
        make_float4(acc[i][0], acc[i][1], acc[i][2], acc[i][3]);
    *(float4*)(crow + 64 + tc * 4) =
        make_float4(acc[i][4], acc[i][5], acc[i][6], acc[i][7]);
  }
}

// ---------------- per-node attention dots: als = h@a_src, ald = h@a_dst ----------------
__global__ __launch_bounds__(256) void dots_kernel(const float* __restrict__ h,
                                                   const float* __restrict__ asrc,
                                                   const float* __restrict__ adst,
                                                   int N, int M) {
  int warp = (blockIdx.x * blockDim.x + threadIdx.x) >> 5;
  int lane = threadIdx.x & 31;
  if (warp >= N) return;
  const float4* row = (const float4*)(h + (size_t)warp * M);
  const float4* av = (const float4*)asrc;
  const float4* bv = (const float4*)adst;
  float s = 0.f, d = 0.f;
  int nv = M >> 7;  // float4 groups of 32 lanes: 2 (M=256) or 1 (M=128)
  for (int v = 0; v < nv; ++v) {
    float4 hv = row[lane + v * 32];
    float4 a = av[lane + v * 32];
    float4 b = bv[lane + v * 32];
    s += hv.x * a.x + hv.y * a.y + hv.z * a.z + hv.w * a.w;
    d += hv.x * b.x + hv.y * b.y + hv.z * b.z + hv.w * b.w;
  }
#pragma unroll
  for (int o = 16; o; o >>= 1) {
    s += __shfl_xor_sync(0xffffffffu, s, o);
    d += __shfl_xor_sync(0xffffffffu, d, o);
  }
  if (lane == 0) { g_als[warp] = s; g_ald[warp] = d; }
}

// ---------------- softmax attention + aggregation (one warp per dst node) ----------------
template <int M, bool RELU>
__global__ __launch_bounds__(256) void attn_agg_kernel(const float* __restrict__ h,
                                                       const float* __restrict__ bias,
                                                       float* __restrict__ out,
                                                       int N) {
  int node = (blockIdx.x * blockDim.x + threadIdx.x) >> 5;
  int lane = threadIdx.x & 31;
  if (node >= N) return;
  int beg = g_rowptr[node];
  int end = g_rowptr[node + 1];
  float aldn = g_ald[node];

  // pass 1: e = leaky_relu(als[src] + ald[dst]), running max
  float mx = -1e30f;
  for (int j = beg + lane; j < end; j += 32) {
    float e = g_als[g_srcs[j]] + aldn;
    e = (e > 0.f) ? e : 0.2f * e;
    g_escr[j] = e;
    mx = fmaxf(mx, e);
  }
#pragma unroll
  for (int o = 16; o; o >>= 1) mx = fmaxf(mx, __shfl_xor_sync(0xffffffffu, mx, o));

  // pass 2: exp(e - m), running sum
  float sum = 0.f;
  for (int j = beg + lane; j < end; j += 32) {
    float ex = __expf(g_escr[j] - mx);
    g_escr[j] = ex;
    sum += ex;
  }
#pragma unroll
  for (int o = 16; o; o >>= 1) sum += __shfl_xor_sync(0xffffffffu, sum, o);
  float inv = 1.f / sum;
  __syncwarp();  // make cross-lane g_escr writes visible before aggregation

  // pass 3: out = sum_j alpha_j * h[src_j]  (float4, lane-striped channels)
  constexpr int NV = M / 128;
  float4 acc[NV];
#pragma unroll
  for (int v = 0; v < NV; ++v) acc[v] = make_float4(0.f, 0.f, 0.f, 0.f);

  for (int j = beg; j < end; ++j) {
    float al = g_escr[j] * inv;
    const float4* row = (const float4*)(h + (size_t)g_srcs[j] * M);
#pragma unroll
    for (int v = 0; v < NV; ++v) {
      float4 hv = __ldg(&row[lane + v * 32]);
      acc[v].x = fmaf(al, hv.x, acc[v].x);
      acc[v].y = fmaf(al, hv.y, acc[v].y);
      acc[v].z = fmaf(al, hv.z, acc[v].z);
      acc[v].w = fmaf(al, hv.w, acc[v].w);
    }
  }

  float4* orow = (float4*)(out + (size_t)node * M);
  const float4* bv = (const float4*)bias;
#pragma unroll
  for (int v = 0; v < NV; ++v) {
    float4 b = bv[lane + v * 32];
    float4 r = make_float4(acc[v].x + b.x, acc[v].y + b.y,
                           acc[v].z + b.z, acc[v].w + b.w);
    if (RELU) {
      r.x = fmaxf(r.x, 0.f); r.y = fmaxf(r.y, 0.f);
      r.z = fmaxf(r.z, 0.f); r.w = fmaxf(r.w, 0.f);
    }
    orow[lane + v * 32] = r;
  }
}

// ---------------- host driver ----------------
extern "C" void kernel_launch(void* const* d_in, const int* in_sizes, int n_in,
                              void* d_out, int out_size) {
  const float* x = (const float*)d_in[0];
  const void* eidx = d_in[1];
  // Weights are always the last 12 inputs (num_graphs may or may not appear).
  const int base = n_in - 12;
  const float* W1  = (const float*)d_in[base + 0];
  const float* as1 = (const float*)d_in[base + 1];
  const float* ad1 = (const float*)d_in[base + 2];
  const float* b1  = (const float*)d_in[base + 3];
  const float* W2  = (const float*)d_in[base + 4];
  const float* as2 = (const float*)d_in[base + 5];
  const float* ad2 = (const float*)d_in[base + 6];
  const float* b2  = (const float*)d_in[base + 7];
  const float* W3  = (const float*)d_in[base + 8];
  const float* as3 = (const float*)d_in[base + 9];
  const float* ad3 = (const float*)d_in[base + 10];
  const float* b3  = (const float*)d_in[base + 11];

  const int N = in_sizes[0] / 128;
  const int E = in_sizes[1] / 2;

  float *bufA, *bufB;
  cudaGetSymbolAddress((void**)&bufA, g_bufA);
  cudaGetSymbolAddress((void**)&bufB, g_bufB);

  // CSR build (once — shared by all 3 layers)
  detect_zero_kernel<<<160, 256>>>(eidx);
  hist_kernel<<<(E + 255) / 256, 256>>>(eidx, E);
  scan_kernel<<<1, 1024>>>(N);
  scatter_kernel<<<(E + N + 255) / 256, 256>>>(eidx, E, N);

  const int gy = (N + 127) / 128;
  const int dots_blocks = (N * 32 + 255) / 256;
  const int agg_blocks = (N + 7) / 8;

  // Layer 1: x[N,128] -> h1[N,256] (relu)
  gemm_kernel<<<dim3(2, gy), 256>>>(x, W1, bufA, N, 128, 256);
  dots_kernel<<<dots_blocks, 256>>>(bufA, as1, ad1, N, 256);
  attn_agg_kernel<256, true><<<agg_blocks, 256>>>(bufA, b1, bufB, N);

  // Layer 2: h1[N,256] -> h2[N,256] (relu)
  gemm_kernel<<<dim3(2, gy), 256>>>(bufB, W2, bufA, N, 256, 256);
  dots_kernel<<<dots_blocks, 256>>>(bufA, as2, ad2, N, 256);
  attn_agg_kernel<256, true><<<agg_blocks, 256>>>(bufA, b2, bufB, N);

  // Layer 3: h2[N,256] -> out[N,128]
  gemm_kernel<<<dim3(1, gy), 256>>>(bufB, W3, bufA, N, 256, 128);
  dots_kernel<<<dots_blocks, 256>>>(bufA, as3, ad3, N, 128);
  attn_agg_kernel<128, false><<<agg_blocks, 256>>>(bufA, b3, (float*)d_out, N);
}

// round 8
// speedup vs baseline: 1.3660x; 1.3660x over previous
#include <cuda_runtime.h>
#include <cuda_bf16.h>
#include <math.h>

// Problem constants (shapes fixed by the reference setup)
#define NMAX   40000
#define EMAX   400000
#define EPRIME (EMAX + NMAX)

// ---------------- device scratch (no allocation allowed) ----------------
__device__ float g_bufA[NMAX * 256];
__device__ float g_bufB[NMAX * 256];
__device__ float g_als[NMAX];
__device__ float g_ald[NMAX];
__device__ float g_escr[EPRIME];      // per-edge e / exp(e-m) scratch (sorted order)
__device__ int   g_deg[NMAX];
__device__ int   g_rowptr[NMAX + 1];
__device__ int   g_cursor[NMAX + 1];
__device__ int   g_srcs[EPRIME];      // src node of each dst-sorted edge
__device__ int   g_is64;

// edge_index may arrive as int64 (reference declares int64) or int32 (default
// JAX x64-disabled). Detected at runtime.
__device__ __forceinline__ int edge_at(const void* p, long long idx) {
  if (g_is64) return (int)((const long long*)p)[idx];
  return ((const int*)p)[idx];
}

// ---------------- CSR build ----------------
__global__ void detect_zero_kernel(const void* __restrict__ eidx) {
  int t = blockIdx.x * blockDim.x + threadIdx.x;
  if (t == 0) {
    const int* p = (const int*)eidx;
    int is64 = 1;
    for (int i = 0; i < 64; ++i) {
      if (p[2 * i + 1] != 0) { is64 = 0; break; }
    }
    g_is64 = is64;
  }
  for (int i = t; i < NMAX; i += gridDim.x * blockDim.x) g_deg[i] = 0;
}

__global__ void hist_kernel(const void* __restrict__ eidx, int E) {
  int t = blockIdx.x * blockDim.x + threadIdx.x;
  if (t >= E) return;
  int d = edge_at(eidx, (long long)E + t);
  atomicAdd(&g_deg[d], 1);
}

__global__ void scan_kernel(int N) {
  const int T = 1024;
  int t = threadIdx.x;
  int per = (N + T - 1) / T;
  int lo = t * per;
  int hi = min(lo + per, N);
  int s = 0;
  for (int i = lo; i < hi; ++i) s += g_deg[i] + 1;  // +1 self loop
  __shared__ int sh[T];
  sh[t] = s;
  __syncthreads();
  for (int off = 1; off < T; off <<= 1) {
    int v = (t >= off) ? sh[t - off] : 0;
    __syncthreads();
    sh[t] += v;
    __syncthreads();
  }
  int run = (t == 0) ? 0 : sh[t - 1];
  for (int i = lo; i < hi; ++i) {
    g_rowptr[i] = run;
    g_cursor[i] = run;
    run += g_deg[i] + 1;
  }
  if (hi == N) { g_rowptr[N] = run; g_cursor[N] = run; }
}

__global__ void scatter_kernel(const void* __restrict__ eidx, int E, int N) {
  int t = blockIdx.x * blockDim.x + threadIdx.x;
  if (t < E) {
    int s = edge_at(eidx, t);
    int d = edge_at(eidx, (long long)E + t);
    int pos = atomicAdd(&g_cursor[d], 1);
    g_srcs[pos] = s;
  } else if (t < E + N) {
    int nd = t - E;                     // self loop
    int pos = atomicAdd(&g_cursor[nd], 1);
    g_srcs[pos] = nd;
  }
}

// ---------------- TF32 tensor-core GEMM: C[N,M] = A[N,K] * W[K,M] ----------
// 128x128 block tile, BK=32, 256 threads = 8 warps (2x4), warp tile 64x32,
// mma.sync.m16n8k8.tf32. Smem padded to 132 -> conflict-free frag loads.

__device__ __forceinline__ unsigned f2tf(float x) {
  unsigned u;
  asm("cvt.rna.tf32.f32 %0, %1;" : "=r"(u) : "f"(x));
  return u;
}

__device__ __forceinline__ void mma_tf32(float c[4],
                                         unsigned a0, unsigned a1,
                                         unsigned a2, unsigned a3,
                                         unsigned b0, unsigned b1) {
  asm volatile(
      "mma.sync.aligned.m16n8k8.row.col.f32.tf32.tf32.f32 "
      "{%0,%1,%2,%3}, {%4,%5,%6,%7}, {%8,%9}, {%0,%1,%2,%3};"
      : "+f"(c[0]), "+f"(c[1]), "+f"(c[2]), "+f"(c[3])
      : "r"(a0), "r"(a1), "r"(a2), "r"(a3), "r"(b0), "r"(b1));
}

__global__ __launch_bounds__(256, 2) void gemm_tc_kernel(
    const float* __restrict__ A, const float* __restrict__ W,
    float* __restrict__ C, int N, int K, int M) {
  __shared__ unsigned As[32][132];   // [k][m]
  __shared__ unsigned Bs[32][132];   // [k][n]
  const int bm = blockIdx.y * 128;
  const int bn = blockIdx.x * 128;
  const int tid = threadIdx.x;
  const int warp = tid >> 5, lane = tid & 31;
  const int wm = (warp >> 2) * 64;   // warp M offset: 0 or 64
  const int wn = (warp & 3) * 32;    // warp N offset: 0/32/64/96
  const int lr = lane >> 2;          // 0..7
  const int lc = lane & 3;           // 0..3

  const int arow = tid >> 1;         // 0..127  (A-tile row this thread loads)
  const int acb  = (tid & 1) * 4;    // A float4-chunk base: 0 or 4
  const int brow = tid >> 3;         // 0..31   (B-tile k-row)
  const int bc4  = tid & 7;          // B float4-col base

  float acc[4][4][4];
#pragma unroll
  for (int i = 0; i < 4; ++i)
#pragma unroll
    for (int j = 0; j < 4; ++j)
#pragma unroll
      for (int q = 0; q < 4; ++q) acc[i][j][q] = 0.f;

  for (int k0 = 0; k0 < K; k0 += 32) {
    // ---- stage A tile (128 rows x 32 k), transposed to [k][m] ----
    {
      int grow = bm + arow;
      const float4* src = (const float4*)(A + (size_t)grow * K + k0);
#pragma unroll
      for (int c = 0; c < 4; ++c) {
        float4 v = make_float4(0.f, 0.f, 0.f, 0.f);
        if (grow < N) v = src[acb + c];
        int kk = (acb + c) * 4;
        As[kk + 0][arow] = f2tf(v.x);
        As[kk + 1][arow] = f2tf(v.y);
        As[kk + 2][arow] = f2tf(v.z);
        As[kk + 3][arow] = f2tf(v.w);
      }
    }
    // ---- stage B tile (32 k x 128 n) ----
    {
      const float4* src = (const float4*)(W + (size_t)(k0 + brow) * M + bn);
#pragma unroll
      for (int j = 0; j < 4; ++j) {
        float4 v = src[bc4 + j * 8];
        int col = (bc4 + j * 8) * 4;
        Bs[brow][col + 0] = f2tf(v.x);
        Bs[brow][col + 1] = f2tf(v.y);
        Bs[brow][col + 2] = f2tf(v.z);
        Bs[brow][col + 3] = f2tf(v.w);
      }
    }
    __syncthreads();

#pragma unroll
    for (int ks = 0; ks < 4; ++ks) {
      const int kb = ks * 8;
      unsigned af[4][4], bf[4][2];
#pragma unroll
      for (int i = 0; i < 4; ++i) {
        int m = wm + i * 16 + lr;
        af[i][0] = As[kb + lc][m];
        af[i][1] = As[kb + lc][m + 8];
        af[i][2] = As[kb + lc + 4][m];
        af[i][3] = As[kb + lc + 4][m + 8];
      }
#pragma unroll
      for (int j = 0; j < 4; ++j) {
        int n = wn + j * 8 + lr;
        bf[j][0] = Bs[kb + lc][n];
        bf[j][1] = Bs[kb + lc + 4][n];
      }
#pragma unroll
      for (int i = 0; i < 4; ++i)
#pragma unroll
        for (int j = 0; j < 4; ++j)
          mma_tf32(acc[i][j], af[i][0], af[i][1], af[i][2], af[i][3],
                   bf[j][0], bf[j][1]);
    }
    __syncthreads();
  }

  // ---- epilogue: fp32 stores (float2 per c-pair) ----
#pragma unroll
  for (int i = 0; i < 4; ++i) {
    int r0 = bm + wm + i * 16 + lr;
#pragma unroll
    for (int j = 0; j < 4; ++j) {
      int cb = bn + wn + j * 8 + lc * 2;
      if (r0 < N)
        *(float2*)(C + (size_t)r0 * M + cb) =
            make_float2(acc[i][j][0], acc[i][j][1]);
      if (r0 + 8 < N)
        *(float2*)(C + (size_t)(r0 + 8) * M + cb) =
            make_float2(acc[i][j][2], acc[i][j][3]);
    }
  }
}

// ---------------- per-node attention dots: als = h@a_src, ald = h@a_dst ----
__global__ __launch_bounds__(256) void dots_kernel(const float* __restrict__ h,
                                                   const float* __restrict__ asrc,
                                                   const float* __restrict__ adst,
                                                   int N, int M) {
  int warp = (blockIdx.x * blockDim.x + threadIdx.x) >> 5;
  int lane = threadIdx.x & 31;
  if (warp >= N) return;
  const float4* row = (const float4*)(h + (size_t)warp * M);
  const float4* av = (const float4*)asrc;
  const float4* bv = (const float4*)adst;
  float s = 0.f, d = 0.f;
  int nv = M >> 7;
  for (int v = 0; v < nv; ++v) {
    float4 hv = row[lane + v * 32];
    float4 a = av[lane + v * 32];
    float4 b = bv[lane + v * 32];
    s += hv.x * a.x + hv.y * a.y + hv.z * a.z + hv.w * a.w;
    d += hv.x * b.x + hv.y * b.y + hv.z * b.z + hv.w * b.w;
  }
#pragma unroll
  for (int o = 16; o; o >>= 1) {
    s += __shfl_xor_sync(0xffffffffu, s, o);
    d += __shfl_xor_sync(0xffffffffu, d, o);
  }
  if (lane == 0) { g_als[warp] = s; g_ald[warp] = d; }
}

// ---------------- softmax attention + aggregation (one warp per dst node) ----
template <int M, bool RELU>
__global__ __launch_bounds__(256) void attn_agg_kernel(const float* __restrict__ h,
                                                       const float* __restrict__ bias,
                                                       float* __restrict__ out,
                                                       int N) {
  int node = (blockIdx.x * blockDim.x + threadIdx.x) >> 5;
  int lane = threadIdx.x & 31;
  if (node >= N) return;
  int beg = g_rowptr[node];
  int end = g_rowptr[node + 1];
  float aldn = g_ald[node];

  // pass 1: e = leaky_relu(als[src] + ald[dst]), running max
  float mx = -1e30f;
  for (int j = beg + lane; j < end; j += 32) {
    float e = g_als[g_srcs[j]] + aldn;
    e = (e > 0.f) ? e : 0.2f * e;
    g_escr[j] = e;
    mx = fmaxf(mx, e);
  }
#pragma unroll
  for (int o = 16; o; o >>= 1) mx = fmaxf(mx, __shfl_xor_sync(0xffffffffu, mx, o));

  // pass 2: exp(e - m), running sum
  float sum = 0.f;
  for (int j = beg + lane; j < end; j += 32) {
    float ex = __expf(g_escr[j] - mx);
    g_escr[j] = ex;
    sum += ex;
  }
#pragma unroll
  for (int o = 16; o; o >>= 1) sum += __shfl_xor_sync(0xffffffffu, sum, o);
  float inv = 1.f / sum;
  __syncwarp();

  // pass 3: out = sum_j alpha_j * h[src_j]
  constexpr int NV = M / 128;
  float4 acc[NV];
#pragma unroll
  for (int v = 0; v < NV; ++v) acc[v] = make_float4(0.f, 0.f, 0.f, 0.f);

  for (int j = beg; j < end; ++j) {
    float al = g_escr[j] * inv;
    const float4* row = (const float4*)(h + (size_t)g_srcs[j] * M);
#pragma unroll
    for (int v = 0; v < NV; ++v) {
      float4 hv = __ldg(&row[lane + v * 32]);
      acc[v].x = fmaf(al, hv.x, acc[v].x);
      acc[v].y = fmaf(al, hv.y, acc[v].y);
      acc[v].z = fmaf(al, hv.z, acc[v].z);
      acc[v].w = fmaf(al, hv.w, acc[v].w);
    }
  }

  float4* orow = (float4*)(out + (size_t)node * M);
  const float4* bv = (const float4*)bias;
#pragma unroll
  for (int v = 0; v < NV; ++v) {
    float4 b = bv[lane + v * 32];
    float4 r = make_float4(acc[v].x + b.x, acc[v].y + b.y,
                           acc[v].z + b.z, acc[v].w + b.w);
    if (RELU) {
      r.x = fmaxf(r.x, 0.f); r.y = fmaxf(r.y, 0.f);
      r.z = fmaxf(r.z, 0.f); r.w = fmaxf(r.w, 0.f);
    }
    orow[lane + v * 32] = r;
  }
}

// ---------------- host driver ----------------
extern "C" void kernel_launch(void* const* d_in, const int* in_sizes, int n_in,
                              void* d_out, int out_size) {
  const float* x = (const float*)d_in[0];
  const void* eidx = d_in[1];
  const int base = n_in - 12;
  const float* W1  = (const float*)d_in[base + 0];
  const float* as1 = (const float*)d_in[base + 1];
  const float* ad1 = (const float*)d_in[base + 2];
  const float* b1  = (const float*)d_in[base + 3];
  const float* W2  = (const float*)d_in[base + 4];
  const float* as2 = (const float*)d_in[base + 5];
  const float* ad2 = (const float*)d_in[base + 6];
  const float* b2  = (const float*)d_in[base + 7];
  const float* W3  = (const float*)d_in[base + 8];
  const float* as3 = (const float*)d_in[base + 9];
  const float* ad3 = (const float*)d_in[base + 10];
  const float* b3  = (const float*)d_in[base + 11];

  const int N = in_sizes[0] / 128;
  const int E = in_sizes[1] / 2;

  float *bufA, *bufB;
  cudaGetSymbolAddress((void**)&bufA, g_bufA);
  cudaGetSymbolAddress((void**)&bufB, g_bufB);

  // CSR build (once — shared by all 3 layers)
  detect_zero_kernel<<<160, 256>>>(eidx);
  hist_kernel<<<(E + 255) / 256, 256>>>(eidx, E);
  scan_kernel<<<1, 1024>>>(N);
  scatter_kernel<<<(E + N + 255) / 256, 256>>>(eidx, E, N);

  const int gy = (N + 127) / 128;
  const int dots_blocks = (N * 32 + 255) / 256;
  const int agg_blocks = (N + 7) / 8;

  // Layer 1: x[N,128] -> h1[N,256] (relu)
  gemm_tc_kernel<<<dim3(2, gy), 256>>>(x, W1, bufA, N, 128, 256);
  dots_kernel<<<dots_blocks, 256>>>(bufA, as1, ad1, N, 256);
  attn_agg_kernel<256, true><<<agg_blocks, 256>>>(bufA, b1, bufB, N);

  // Layer 2: h1[N,256] -> h2[N,256] (relu)
  gemm_tc_kernel<<<dim3(2, gy), 256>>>(bufB, W2, bufA, N, 256, 256);
  dots_kernel<<<dots_blocks, 256>>>(bufA, as2, ad2, N, 256);
  attn_agg_kernel<256, true><<<agg_blocks, 256>>>(bufA, b2, bufB, N);

  // Layer 3: h2[N,256] -> out[N,128]
  gemm_tc_kernel<<<dim3(1, gy), 256>>>(bufB, W3, bufA, N, 256, 128);
  dots_kernel<<<dots_blocks, 256>>>(bufA, as3, ad3, N, 128);
  attn_agg_kernel<128, false><<<agg_blocks, 256>>>(bufA, b3, (float*)d_out, N);
}

// round 9
// speedup vs baseline: 1.4472x; 1.0595x over previous
#include <cuda_runtime.h>
#include <cuda_bf16.h>
#include <math.h>

// Problem constants (shapes fixed by the reference setup)
#define NMAX   40000
#define EMAX   400000
#define EPRIME (EMAX + NMAX)

// ---------------- device scratch (no allocation allowed) ----------------
__device__ float g_bufA[NMAX * 256];
__device__ float g_bufB[NMAX * 256];
__device__ float g_alsA[NMAX], g_aldA[NMAX];
__device__ float g_alsB[NMAX], g_aldB[NMAX];
__device__ float g_alsC[NMAX], g_aldC[NMAX];
__device__ float g_escr[EPRIME];      // fallback scratch for high-degree nodes
__device__ int   g_deg[NMAX];
__device__ int   g_rowptr[NMAX + 1];
__device__ int   g_cursor[NMAX + 1];
__device__ int   g_srcs[EPRIME];      // src node of each dst-sorted edge
__device__ int   g_is64;

// edge_index may arrive as int64 (reference declares int64) or int32 (default
// JAX x64-disabled). Detected at runtime.
__device__ __forceinline__ int edge_at(const void* p, long long idx) {
  if (g_is64) return (int)((const long long*)p)[idx];
  return ((const int*)p)[idx];
}

// ---------------- init: dtype detect + zero deg + zero dot accumulators ----
__global__ void init_kernel(const void* __restrict__ eidx) {
  int t = blockIdx.x * blockDim.x + threadIdx.x;
  if (t == 0) {
    const int* p = (const int*)eidx;
    int is64 = 1;
    for (int i = 0; i < 64; ++i) {
      if (p[2 * i + 1] != 0) { is64 = 0; break; }
    }
    g_is64 = is64;
  }
  for (int i = t; i < NMAX; i += gridDim.x * blockDim.x) {
    g_deg[i] = 0;
    g_alsA[i] = 0.f; g_aldA[i] = 0.f;
    g_alsB[i] = 0.f; g_aldB[i] = 0.f;
    g_alsC[i] = 0.f; g_aldC[i] = 0.f;
  }
}

__global__ void hist_kernel(const void* __restrict__ eidx, int E) {
  int t = blockIdx.x * blockDim.x + threadIdx.x;
  if (t >= E) return;
  int d = edge_at(eidx, (long long)E + t);
  atomicAdd(&g_deg[d], 1);
}

__global__ void scan_kernel(int N) {
  const int T = 1024;
  int t = threadIdx.x;
  int per = (N + T - 1) / T;
  int lo = t * per;
  int hi = min(lo + per, N);
  int s = 0;
  for (int i = lo; i < hi; ++i) s += g_deg[i] + 1;  // +1 self loop
  __shared__ int sh[T];
  sh[t] = s;
  __syncthreads();
  for (int off = 1; off < T; off <<= 1) {
    int v = (t >= off) ? sh[t - off] : 0;
    __syncthreads();
    sh[t] += v;
    __syncthreads();
  }
  int run = (t == 0) ? 0 : sh[t - 1];
  for (int i = lo; i < hi; ++i) {
    g_rowptr[i] = run;
    g_cursor[i] = run;
    run += g_deg[i] + 1;
  }
  if (hi == N) { g_rowptr[N] = run; g_cursor[N] = run; }
}

__global__ void scatter_kernel(const void* __restrict__ eidx, int E, int N) {
  int t = blockIdx.x * blockDim.x + threadIdx.x;
  if (t < E) {
    int s = edge_at(eidx, t);
    int d = edge_at(eidx, (long long)E + t);
    int pos = atomicAdd(&g_cursor[d], 1);
    g_srcs[pos] = s;
  } else if (t < E + N) {
    int nd = t - E;                     // self loop
    int pos = atomicAdd(&g_cursor[nd], 1);
    g_srcs[pos] = nd;
  }
}

// ---------------- TF32 tensor-core GEMM + fused attention dots -------------
// C[N,M] = A[N,K] * W[K,M]; also atomically accumulates als = C@a_src,
// ald = C@a_dst into pre-zeroed arrays.
// 128x128 block tile, BK=32, 256 threads = 8 warps (2x4), warp tile 64x32.
// Raw fp32 staged in smem (reg-double-buffered LDG); cvt.rna at frag load.

__device__ __forceinline__ unsigned f2tf(float x) {
  unsigned u;
  asm("cvt.rna.tf32.f32 %0, %1;" : "=r"(u) : "f"(x));
  return u;
}

__device__ __forceinline__ void mma_tf32(float c[4],
                                         unsigned a0, unsigned a1,
                                         unsigned a2, unsigned a3,
                                         unsigned b0, unsigned b1) {
  asm volatile(
      "mma.sync.aligned.m16n8k8.row.col.f32.tf32.tf32.f32 "
      "{%0,%1,%2,%3}, {%4,%5,%6,%7}, {%8,%9}, {%0,%1,%2,%3};"
      : "+f"(c[0]), "+f"(c[1]), "+f"(c[2]), "+f"(c[3])
      : "r"(a0), "r"(a1), "r"(a2), "r"(a3), "r"(b0), "r"(b1));
}

__global__ __launch_bounds__(256) void gemm_tc_kernel(
    const float* __restrict__ A, const float* __restrict__ W,
    float* __restrict__ C,
    const float* __restrict__ avs, const float* __restrict__ avd,
    float* __restrict__ als, float* __restrict__ ald,
    int N, int K, int M) {
  __shared__ float As[32][132];   // [k][m]
  __shared__ float Bs[32][132];   // [k][n]
  const int bm = blockIdx.y * 128;
  const int bn = blockIdx.x * 128;
  const int tid = threadIdx.x;
  const int warp = tid >> 5, lane = tid & 31;
  const int wm = (warp >> 2) * 64;   // warp M offset: 0 or 64
  const int wn = (warp & 3) * 32;    // warp N offset: 0/32/64/96
  const int lr = lane >> 2;          // 0..7
  const int lc = lane & 3;           // 0..3

  const int arow = tid >> 1;         // 0..127  (A-tile row this thread loads)
  const int acb  = (tid & 1) * 4;    // A float4-chunk base: 0 or 4
  const int brow = tid >> 3;         // 0..31   (B-tile k-row)
  const int bc4  = tid & 7;          // B float4-col base

  const bool rok = (bm + arow) < N;
  const float* Arow = A + (size_t)(bm + arow) * K;

  float acc[4][4][4];
#pragma unroll
  for (int i = 0; i < 4; ++i)
#pragma unroll
    for (int j = 0; j < 4; ++j)
#pragma unroll
      for (int q = 0; q < 4; ++q) acc[i][j][q] = 0.f;

  // prologue: load k0=0 tile into registers
  float4 ra[4], rb[4];
#pragma unroll
  for (int c = 0; c < 4; ++c)
    ra[c] = rok ? *(const float4*)(Arow + (acb + c) * 4)
                : make_float4(0.f, 0.f, 0.f, 0.f);
  {
    const float* Wrow = W + (size_t)brow * M + bn;
#pragma unroll
    for (int j = 0; j < 4; ++j)
      rb[j] = *(const float4*)(Wrow + bc4 * 4 + j * 32);
  }

  for (int k0 = 0; k0 < K; k0 += 32) {
    // commit staged registers to smem
#pragma unroll
    for (int c = 0; c < 4; ++c) {
      int kk = (acb + c) * 4;
      As[kk + 0][arow] = ra[c].x;
      As[kk + 1][arow] = ra[c].y;
      As[kk + 2][arow] = ra[c].z;
      As[kk + 3][arow] = ra[c].w;
    }
#pragma unroll
    for (int j = 0; j < 4; ++j)
      *(float4*)&Bs[brow][bc4 * 4 + j * 32] = rb[j];
    __syncthreads();

    // prefetch next tile (overlaps with mma below)
    if (k0 + 32 < K) {
#pragma unroll
      for (int c = 0; c < 4; ++c)
        ra[c] = rok ? *(const float4*)(Arow + k0 + 32 + (acb + c) * 4)
                    : make_float4(0.f, 0.f, 0.f, 0.f);
      const float* Wrow = W + (size_t)(k0 + 32 + brow) * M + bn;
#pragma unroll
      for (int j = 0; j < 4; ++j)
        rb[j] = *(const float4*)(Wrow + bc4 * 4 + j * 32);
    }

#pragma unroll
    for (int ks = 0; ks < 4; ++ks) {
      const int kb = ks * 8;
      unsigned af[4][4], bf[4][2];
#pragma unroll
      for (int i = 0; i < 4; ++i) {
        int m = wm + i * 16 + lr;
        af[i][0] = f2tf(As[kb + lc][m]);
        af[i][1] = f2tf(As[kb + lc][m + 8]);
        af[i][2] = f2tf(As[kb + lc + 4][m]);
        af[i][3] = f2tf(As[kb + lc + 4][m + 8]);
      }
#pragma unroll
      for (int j = 0; j < 4; ++j) {
        int n = wn + j * 8 + lr;
        bf[j][0] = f2tf(Bs[kb + lc][n]);
        bf[j][1] = f2tf(Bs[kb + lc + 4][n]);
      }
#pragma unroll
      for (int i = 0; i < 4; ++i)
#pragma unroll
        for (int j = 0; j < 4; ++j)
          mma_tf32(acc[i][j], af[i][0], af[i][1], af[i][2], af[i][3],
                   bf[j][0], bf[j][1]);
    }
    __syncthreads();
  }

  // ---- epilogue: fp32 stores + fused a_src/a_dst dot partials ----
  float avsv[4][2], avdv[4][2];
#pragma unroll
  for (int j = 0; j < 4; ++j) {
    int cb = bn + wn + j * 8 + lc * 2;
    avsv[j][0] = avs[cb]; avsv[j][1] = avs[cb + 1];
    avdv[j][0] = avd[cb]; avdv[j][1] = avd[cb + 1];
  }

#pragma unroll
  for (int i = 0; i < 4; ++i) {
    int r0 = bm + wm + i * 16 + lr;
    float s0 = 0.f, d0 = 0.f, s1 = 0.f, d1 = 0.f;
#pragma unroll
    for (int j = 0; j < 4; ++j) {
      int cb = bn + wn + j * 8 + lc * 2;
      if (r0 < N)
        *(float2*)(C + (size_t)r0 * M + cb) =
            make_float2(acc[i][j][0], acc[i][j][1]);
      if (r0 + 8 < N)
        *(float2*)(C + (size_t)(r0 + 8) * M + cb) =
            make_float2(acc[i][j][2], acc[i][j][3]);
      s0 = fmaf(avsv[j][0], acc[i][j][0], fmaf(avsv[j][1], acc[i][j][1], s0));
      d0 = fmaf(avdv[j][0], acc[i][j][0], fmaf(avdv[j][1], acc[i][j][1], d0));
      s1 = fmaf(avsv[j][0], acc[i][j][2], fmaf(avsv[j][1], acc[i][j][3], s1));
      d1 = fmaf(avdv[j][0], acc[i][j][2], fmaf(avdv[j][1], acc[i][j][3], d1));
    }
    // reduce across the 4 lanes (lc = 0..3) sharing each row
#pragma unroll
    for (int o = 1; o < 4; o <<= 1) {
      s0 += __shfl_xor_sync(0xffffffffu, s0, o);
      d0 += __shfl_xor_sync(0xffffffffu, d0, o);
      s1 += __shfl_xor_sync(0xffffffffu, s1, o);
      d1 += __shfl_xor_sync(0xffffffffu, d1, o);
    }
    if (lc == 0) {
      if (r0 < N)     { atomicAdd(&als[r0], s0);     atomicAdd(&ald[r0], d0); }
      if (r0 + 8 < N) { atomicAdd(&als[r0 + 8], s1); atomicAdd(&ald[r0 + 8], d1); }
    }
  }
}

// ---------------- softmax attention + aggregation (one warp per dst node) ----
// Register-resident e/exp for deg <= 64 (always, in practice: Poisson(10));
// global-scratch fallback for larger degrees.
template <int M, bool RELU>
__global__ __launch_bounds__(256) void attn_agg_kernel(
    const float* __restrict__ h, const float* __restrict__ bias,
    float* __restrict__ out,
    const float* __restrict__ als, const float* __restrict__ ald, int N) {
  int node = (blockIdx.x * blockDim.x + threadIdx.x) >> 5;
  int lane = threadIdx.x & 31;
  if (node >= N) return;
  int beg = g_rowptr[node];
  int end = g_rowptr[node + 1];
  int deg = end - beg;
  float aldn = ald[node];

  constexpr int NV = M / 128;
  float4 acc[NV];
#pragma unroll
  for (int v = 0; v < NV; ++v) acc[v] = make_float4(0.f, 0.f, 0.f, 0.f);

  if (deg <= 64) {
    // ---- fused register path ----
    int s0 = 0, s1 = 0;
    float e0 = -1e30f, e1 = -1e30f;
    if (lane < deg) {
      s0 = g_srcs[beg + lane];
      float e = als[s0] + aldn;
      e0 = (e > 0.f) ? e : 0.2f * e;
    }
    if (32 + lane < deg) {
      s1 = g_srcs[beg + 32 + lane];
      float e = als[s1] + aldn;
      e1 = (e > 0.f) ? e : 0.2f * e;
    }
    float mx = fmaxf(e0, e1);
#pragma unroll
    for (int o = 16; o; o >>= 1)
      mx = fmaxf(mx, __shfl_xor_sync(0xffffffffu, mx, o));
    float ex0 = (lane < deg) ? __expf(e0 - mx) : 0.f;
    float ex1 = (32 + lane < deg) ? __expf(e1 - mx) : 0.f;
    float sum = ex0 + ex1;
#pragma unroll
    for (int o = 16; o; o >>= 1)
      sum += __shfl_xor_sync(0xffffffffu, sum, o);
    float inv = 1.f / sum;

    int jj = 0;
    for (; jj + 2 <= deg; jj += 2) {
      int   ls0 = __shfl_sync(0xffffffffu, (jj < 32) ? s0 : s1, jj & 31);
      float le0 = __shfl_sync(0xffffffffu, (jj < 32) ? ex0 : ex1, jj & 31);
      int   ls1 = __shfl_sync(0xffffffffu, (jj + 1 < 32) ? s0 : s1, (jj + 1) & 31);
      float le1 = __shfl_sync(0xffffffffu, (jj + 1 < 32) ? ex0 : ex1, (jj + 1) & 31);
      float al0 = le0 * inv, al1 = le1 * inv;
      const float4* rp0 = (const float4*)(h + (size_t)ls0 * M);
      const float4* rp1 = (const float4*)(h + (size_t)ls1 * M);
      float4 h0[NV], h1[NV];
#pragma unroll
      for (int v = 0; v < NV; ++v) {
        h0[v] = __ldg(&rp0[lane + v * 32]);
        h1[v] = __ldg(&rp1[lane + v * 32]);
      }
#pragma unroll
      for (int v = 0; v < NV; ++v) {
        acc[v].x = fmaf(al0, h0[v].x, fmaf(al1, h1[v].x, acc[v].x));
        acc[v].y = fmaf(al0, h0[v].y, fmaf(al1, h1[v].y, acc[v].y));
        acc[v].z = fmaf(al0, h0[v].z, fmaf(al1, h1[v].z, acc[v].z));
        acc[v].w = fmaf(al0, h0[v].w, fmaf(al1, h1[v].w, acc[v].w));
      }
    }
    if (jj < deg) {
      int   ls0 = __shfl_sync(0xffffffffu, (jj < 32) ? s0 : s1, jj & 31);
      float le0 = __shfl_sync(0xffffffffu, (jj < 32) ? ex0 : ex1, jj & 31);
      float al0 = le0 * inv;
      const float4* rp0 = (const float4*)(h + (size_t)ls0 * M);
#pragma unroll
      for (int v = 0; v < NV; ++v) {
        float4 hv = __ldg(&rp0[lane + v * 32]);
        acc[v].x = fmaf(al0, hv.x, acc[v].x);
        acc[v].y = fmaf(al0, hv.y, acc[v].y);
        acc[v].z = fmaf(al0, hv.z, acc[v].z);
        acc[v].w = fmaf(al0, hv.w, acc[v].w);
      }
    }
  } else {
    // ---- fallback: global scratch (rare / impossible for this dataset) ----
    float mx = -1e30f;
    for (int j = beg + lane; j < end; j += 32) {
      float e = als[g_srcs[j]] + aldn;
      e = (e > 0.f) ? e : 0.2f * e;
      g_escr[j] = e;
      mx = fmaxf(mx, e);
    }
#pragma unroll
    for (int o = 16; o; o >>= 1)
      mx = fmaxf(mx, __shfl_xor_sync(0xffffffffu, mx, o));
    float sum = 0.f;
    for (int j = beg + lane; j < end; j += 32) {
      float ex = __expf(g_escr[j] - mx);
      g_escr[j] = ex;
      sum += ex;
    }
#pragma unroll
    for (int o = 16; o; o >>= 1)
      sum += __shfl_xor_sync(0xffffffffu, sum, o);
    float inv = 1.f / sum;
    __syncwarp();
    for (int j = beg; j < end; ++j) {
      float al = g_escr[j] * inv;
      const float4* row = (const float4*)(h + (size_t)g_srcs[j] * M);
#pragma unroll
      for (int v = 0; v < NV; ++v) {
        float4 hv = __ldg(&row[lane + v * 32]);
        acc[v].x = fmaf(al, hv.x, acc[v].x);
        acc[v].y = fmaf(al, hv.y, acc[v].y);
        acc[v].z = fmaf(al, hv.z, acc[v].z);
        acc[v].w = fmaf(al, hv.w, acc[v].w);
      }
    }
  }

  float4* orow = (float4*)(out + (size_t)node * M);
  const float4* bv = (const float4*)bias;
#pragma unroll
  for (int v = 0; v < NV; ++v) {
    float4 b = bv[lane + v * 32];
    float4 r = make_float4(acc[v].x + b.x, acc[v].y + b.y,
                           acc[v].z + b.z, acc[v].w + b.w);
    if (RELU) {
      r.x = fmaxf(r.x, 0.f); r.y = fmaxf(r.y, 0.f);
      r.z = fmaxf(r.z, 0.f); r.w = fmaxf(r.w, 0.f);
    }
    orow[lane + v * 32] = r;
  }
}

// ---------------- host driver ----------------
extern "C" void kernel_launch(void* const* d_in, const int* in_sizes, int n_in,
                              void* d_out, int out_size) {
  const float* x = (const float*)d_in[0];
  const void* eidx = d_in[1];
  const int base = n_in - 12;
  const float* W1  = (const float*)d_in[base + 0];
  const float* as1 = (const float*)d_in[base + 1];
  const float* ad1 = (const float*)d_in[base + 2];
  const float* b1  = (const float*)d_in[base + 3];
  const float* W2  = (const float*)d_in[base + 4];
  const float* as2 = (const float*)d_in[base + 5];
  const float* ad2 = (const float*)d_in[base + 6];
  const float* b2  = (const float*)d_in[base + 7];
  const float* W3  = (const float*)d_in[base + 8];
  const float* as3 = (const float*)d_in[base + 9];
  const float* ad3 = (const float*)d_in[base + 10];
  const float* b3  = (const float*)d_in[base + 11];

  const int N = in_sizes[0] / 128;
  const int E = in_sizes[1] / 2;

  float *bufA, *bufB;
  float *alsA, *aldA, *alsB, *aldB, *alsC, *aldC;
  cudaGetSymbolAddress((void**)&bufA, g_bufA);
  cudaGetSymbolAddress((void**)&bufB, g_bufB);
  cudaGetSymbolAddress((void**)&alsA, g_alsA);
  cudaGetSymbolAddress((void**)&aldA, g_aldA);
  cudaGetSymbolAddress((void**)&alsB, g_alsB);
  cudaGetSymbolAddress((void**)&aldB, g_aldB);
  cudaGetSymbolAddress((void**)&alsC, g_alsC);
  cudaGetSymbolAddress((void**)&aldC, g_aldC);

  // CSR build (once — shared by all 3 layers) + zero dot accumulators
  init_kernel<<<160, 256>>>(eidx);
  hist_kernel<<<(E + 255) / 256, 256>>>(eidx, E);
  scan_kernel<<<1, 1024>>>(N);
  scatter_kernel<<<(E + N + 255) / 256, 256>>>(eidx, E, N);

  const int gy = (N + 127) / 128;
  const int agg_blocks = (N + 7) / 8;

  // Layer 1: x[N,128] -> h1[N,256] (relu)
  gemm_tc_kernel<<<dim3(2, gy), 256>>>(x, W1, bufA, as1, ad1, alsA, aldA, N, 128, 256);
  attn_agg_kernel<256, true><<<agg_blocks, 256>>>(bufA, b1, bufB, alsA, aldA, N);

  // Layer 2: h1[N,256] -> h2[N,256] (relu)
  gemm_tc_kernel<<<dim3(2, gy), 256>>>(bufB, W2, bufA, as2, ad2, alsB, aldB, N, 256, 256);
  attn_agg_kernel<256, true><<<agg_blocks, 256>>>(bufA, b2, bufB, alsB, aldB, N);

  // Layer 3: h2[N,256] -> out[N,128]
  gemm_tc_kernel<<<dim3(1, gy), 256>>>(bufB, W3, bufA, as3, ad3, alsC, aldC, N, 256, 128);
  attn_agg_kernel<128, false><<<agg_blocks, 256>>>(bufA, b3, (float*)d_out, alsC, aldC, N);
}

// round 12
// speedup vs baseline: 1.5328x; 1.0592x over previous
#include <cuda_runtime.h>
#include <cuda_bf16.h>
#include <math.h>

// Problem constants (shapes fixed by the reference setup)
#define NMAX   40000
#define EMAX   400000
#define EPRIME (EMAX + NMAX)

// ---------------- device scratch (no allocation allowed) ----------------
// bufA holds h as packed bf16 (M/2 uint32 per row). bufB holds fp32 agg output.
__device__ unsigned g_bufA[NMAX * 128];   // bf16x2: up to 256 cols
__device__ float    g_bufB[NMAX * 256];
__device__ float g_alsA[NMAX], g_aldA[NMAX];
__device__ float g_alsB[NMAX], g_aldB[NMAX];
__device__ float g_alsC[NMAX], g_aldC[NMAX];
__device__ float g_escr[EPRIME];      // fallback scratch for high-degree nodes
__device__ int   g_deg[NMAX];
__device__ int   g_rowptr[NMAX + 1];
__device__ int   g_cursor[NMAX + 1];
__device__ int   g_srcs[EPRIME];      // src node of each dst-sorted edge
__device__ int   g_is64;

// edge_index may arrive as int64 (reference declares int64) or int32 (default
// JAX x64-disabled). Detected at runtime.
__device__ __forceinline__ int edge_at(const void* p, long long idx) {
  if (g_is64) return (int)((const long long*)p)[idx];
  return ((const int*)p)[idx];
}

// ---------------- init: dtype detect + zero deg + zero dot accumulators ----
__global__ void init_kernel(const void* __restrict__ eidx) {
  int t = blockIdx.x * blockDim.x + threadIdx.x;
  if (t == 0) {
    const int* p = (const int*)eidx;
    int is64 = 1;
    for (int i = 0; i < 64; ++i) {
      if (p[2 * i + 1] != 0) { is64 = 0; break; }
    }
    g_is64 = is64;
  }
  for (int i = t; i < NMAX; i += gridDim.x * blockDim.x) {
    g_deg[i] = 0;
    g_alsA[i] = 0.f; g_aldA[i] = 0.f;
    g_alsB[i] = 0.f; g_aldB[i] = 0.f;
    g_alsC[i] = 0.f; g_aldC[i] = 0.f;
  }
}

__global__ void hist_kernel(const void* __restrict__ eidx, int E) {
  int t = blockIdx.x * blockDim.x + threadIdx.x;
  if (t >= E) return;
  int d = edge_at(eidx, (long long)E + t);
  atomicAdd(&g_deg[d], 1);
}

__global__ void scan_kernel(int N) {
  const int T = 1024;
  int t = threadIdx.x;
  int per = (N + T - 1) / T;
  int lo = t * per;
  int hi = min(lo + per, N);
  int s = 0;
  for (int i = lo; i < hi; ++i) s += g_deg[i] + 1;  // +1 self loop
  __shared__ int sh[T];
  sh[t] = s;
  __syncthreads();
  for (int off = 1; off < T; off <<= 1) {
    int v = (t >= off) ? sh[t - off] : 0;
    __syncthreads();
    sh[t] += v;
    __syncthreads();
  }
  int run = (t == 0) ? 0 : sh[t - 1];
  for (int i = lo; i < hi; ++i) {
    g_rowptr[i] = run;
    g_cursor[i] = run;
    run += g_deg[i] + 1;
  }
  if (hi == N) { g_rowptr[N] = run; g_cursor[N] = run; }
}

__global__ void scatter_kernel(const void* __restrict__ eidx, int E, int N) {
  int t = blockIdx.x * blockDim.x + threadIdx.x;
  if (t < E) {
    int s = edge_at(eidx, t);
    int d = edge_at(eidx, (long long)E + t);
    int pos = atomicAdd(&g_cursor[d], 1);
    g_srcs[pos] = s;
  } else if (t < E + N) {
    int nd = t - E;                     // self loop
    int pos = atomicAdd(&g_cursor[nd], 1);
    g_srcs[pos] = nd;
  }
}

// ---------------- TF32 tensor-core GEMM + fused attention dots -------------
// C(bf16x2)[N,M] = A[N,K] * W[K,M]; also atomically accumulates the fp32
// dots als = C@a_src, ald = C@a_dst into pre-zeroed arrays.
// 128x128 block tile, BK=32, 256 threads = 8 warps (2x4), warp tile 64x32.
// tf32 conversion happens at the smem commit (off the MMA critical path);
// global loads are register double-buffered across the k-loop.

__device__ __forceinline__ unsigned f2tf(float x) {
  unsigned u;
  asm("cvt.rna.tf32.f32 %0, %1;" : "=r"(u) : "f"(x));
  return u;
}

__device__ __forceinline__ unsigned pack_bf16(float lo, float hi) {
  unsigned u;
  asm("cvt.rn.bf16x2.f32 %0, %1, %2;" : "=r"(u) : "f"(hi), "f"(lo));
  return u;
}

__device__ __forceinline__ void mma_tf32(float c[4],
                                         unsigned a0, unsigned a1,
                                         unsigned a2, unsigned a3,
                                         unsigned b0, unsigned b1) {
  asm volatile(
      "mma.sync.aligned.m16n8k8.row.col.f32.tf32.tf32.f32 "
      "{%0,%1,%2,%3}, {%4,%5,%6,%7}, {%8,%9}, {%0,%1,%2,%3};"
      : "+f"(c[0]), "+f"(c[1]), "+f"(c[2]), "+f"(c[3])
      : "r"(a0), "r"(a1), "r"(a2), "r"(a3), "r"(b0), "r"(b1));
}

__global__ __launch_bounds__(256) void gemm_tc_kernel(
    const float* __restrict__ A, const float* __restrict__ W,
    unsigned* __restrict__ C,              // bf16x2 packed, M/2 words per row
    const float* __restrict__ avs, const float* __restrict__ avd,
    float* __restrict__ als, float* __restrict__ ald,
    int N, int K, int M) {
  __shared__ unsigned As[32][132];   // [k][m]  (tf32 bits)
  __shared__ unsigned Bs[32][132];   // [k][n]  (tf32 bits)
  const int bm = blockIdx.y * 128;
  const int bn = blockIdx.x * 128;
  const int tid = threadIdx.x;
  const int warp = tid >> 5, lane = tid & 31;
  const int wm = (warp >> 2) * 64;   // warp M offset: 0 or 64
  const int wn = (warp & 3) * 32;    // warp N offset: 0/32/64/96
  const int lr = lane >> 2;          // 0..7
  const int lc = lane & 3;           // 0..3

  const int arow = tid >> 1;         // 0..127  (A-tile row this thread loads)
  const int acb  = (tid & 1) * 4;    // A float4-chunk base: 0 or 4
  const int brow = tid >> 3;         // 0..31   (B-tile k-row)
  const int bc4  = tid & 7;          // B float4-col base

  const bool rok = (bm + arow) < N;
  const float* Arow = A + (size_t)(bm + arow) * K;

  float acc[4][4][4];
#pragma unroll
  for (int i = 0; i < 4; ++i)
#pragma unroll
    for (int j = 0; j < 4; ++j)
#pragma unroll
      for (int q = 0; q < 4; ++q) acc[i][j][q] = 0.f;

  // prologue: load k0=0 tile into registers
  float4 ra[4], rb[4];
#pragma unroll
  for (int c = 0; c < 4; ++c)
    ra[c] = rok ? *(const float4*)(Arow + (acb + c) * 4)
                : make_float4(0.f, 0.f, 0.f, 0.f);
  {
    const float* Wrow = W + (size_t)brow * M + bn;
#pragma unroll
    for (int j = 0; j < 4; ++j)
      rb[j] = *(const float4*)(Wrow + bc4 * 4 + j * 32);
  }

  for (int k0 = 0; k0 < K; k0 += 32) {
    // commit staged registers to smem (tf32 conversion here, not in MMA loop)
#pragma unroll
    for (int c = 0; c < 4; ++c) {
      int kk = (acb + c) * 4;
      As[kk + 0][arow] = f2tf(ra[c].x);
      As[kk + 1][arow] = f2tf(ra[c].y);
      As[kk + 2][arow] = f2tf(ra[c].z);
      As[kk + 3][arow] = f2tf(ra[c].w);
    }
#pragma unroll
    for (int j = 0; j < 4; ++j)
      *(uint4*)&Bs[brow][bc4 * 4 + j * 32] =
          make_uint4(f2tf(rb[j].x), f2tf(rb[j].y), f2tf(rb[j].z), f2tf(rb[j].w));
    __syncthreads();

    // prefetch next tile (overlaps with mma below)
    if (k0 + 32 < K) {
#pragma unroll
      for (int c = 0; c < 4; ++c)
        ra[c] = rok ? *(const float4*)(Arow + k0 + 32 + (acb + c) * 4)
                    : make_float4(0.f, 0.f, 0.f, 0.f);
      const float* Wrow = W + (size_t)(k0 + 32 + brow) * M + bn;
#pragma unroll
      for (int j = 0; j < 4; ++j)
        rb[j] = *(const float4*)(Wrow + bc4 * 4 + j * 32);
    }

#pragma unroll
    for (int ks = 0; ks < 4; ++ks) {
      const int kb = ks * 8;
      unsigned af[4][4], bf[4][2];
#pragma unroll
      for (int i = 0; i < 4; ++i) {
        int m = wm + i * 16 + lr;
        af[i][0] = As[kb + lc][m];
        af[i][1] = As[kb + lc][m + 8];
        af[i][2] = As[kb + lc + 4][m];
        af[i][3] = As[kb + lc + 4][m + 8];
      }
#pragma unroll
      for (int j = 0; j < 4; ++j) {
        int n = wn + j * 8 + lr;
        bf[j][0] = Bs[kb + lc][n];
        bf[j][1] = Bs[kb + lc + 4][n];
      }
#pragma unroll
      for (int i = 0; i < 4; ++i)
#pragma unroll
        for (int j = 0; j < 4; ++j)
          mma_tf32(acc[i][j], af[i][0], af[i][1], af[i][2], af[i][3],
                   bf[j][0], bf[j][1]);
    }
    __syncthreads();
  }

  // ---- epilogue: bf16x2 stores + fused a_src/a_dst dot partials (fp32) ----
  float avsv[4][2], avdv[4][2];
#pragma unroll
  for (int j = 0; j < 4; ++j) {
    int cb = bn + wn + j * 8 + lc * 2;
    avsv[j][0] = avs[cb]; avsv[j][1] = avs[cb + 1];
    avdv[j][0] = avd[cb]; avdv[j][1] = avd[cb + 1];
  }

  const int Mw = M >> 1;  // words per row
#pragma unroll
  for (int i = 0; i < 4; ++i) {
    int r0 = bm + wm + i * 16 + lr;
    float s0 = 0.f, d0 = 0.f, s1 = 0.f, d1 = 0.f;
#pragma unroll
    for (int j = 0; j < 4; ++j) {
      int cb = bn + wn + j * 8 + lc * 2;
      if (r0 < N)
        C[(size_t)r0 * Mw + (cb >> 1)] = pack_bf16(acc[i][j][0], acc[i][j][1]);
      if (r0 + 8 < N)
        C[(size_t)(r0 + 8) * Mw + (cb >> 1)] =
            pack_bf16(acc[i][j][2], acc[i][j][3]);
      s0 = fmaf(avsv[j][0], acc[i][j][0], fmaf(avsv[j][1], acc[i][j][1], s0));
      d0 = fmaf(avdv[j][0], acc[i][j][0], fmaf(avdv[j][1], acc[i][j][1], d0));
      s1 = fmaf(avsv[j][0], acc[i][j][2], fmaf(avsv[j][1], acc[i][j][3], s1));
      d1 = fmaf(avdv[j][0], acc[i][j][2], fmaf(avdv[j][1], acc[i][j][3], d1));
    }
    // reduce across the 4 lanes (lc = 0..3) sharing each row
#pragma unroll
    for (int o = 1; o < 4; o <<= 1) {
      s0 += __shfl_xor_sync(0xffffffffu, s0, o);
      d0 += __shfl_xor_sync(0xffffffffu, d0, o);
      s1 += __shfl_xor_sync(0xffffffffu, s1, o);
      d1 += __shfl_xor_sync(0xffffffffu, d1, o);
    }
    if (lc == 0) {
      if (r0 < N)     { atomicAdd(&als[r0], s0);     atomicAdd(&ald[r0], d0); }
      if (r0 + 8 < N) { atomicAdd(&als[r0 + 8], s1); atomicAdd(&ald[r0 + 8], d1); }
    }
  }
}

// bf16 bit-exact unpack (bf16 is truncated fp32): 2 ALU ops per pair
__device__ __forceinline__ float blo(unsigned u) { return __uint_as_float(u << 16); }
__device__ __forceinline__ float bhi(unsigned u) { return __uint_as_float(u & 0xffff0000u); }

// ---------------- softmax attention + aggregation (one warp per dst node) ----
// h is packed bf16x2. Register-resident e/exp for deg <= 64; global-scratch
// fallback for larger degrees (impossible for this dataset: Poisson(10)+1).
template <int M, bool RELU>
__global__ __launch_bounds__(256) void attn_agg_kernel(
    const unsigned* __restrict__ h, const float* __restrict__ bias,
    float* __restrict__ out,
    const float* __restrict__ als, const float* __restrict__ ald, int N) {
  int node = (blockIdx.x * blockDim.x + threadIdx.x) >> 5;
  int lane = threadIdx.x & 31;
  if (node >= N) return;
  int beg = g_rowptr[node];
  int end = g_rowptr[node + 1];
  int deg = end - beg;
  float aldn = ald[node];

  constexpr int Mw = M >> 1;        // words per row
  constexpr int NW = Mw / 32;       // words per lane: 4 (M=256) or 2 (M=128)
  float acc[NW * 2];
#pragma unroll
  for (int q = 0; q < NW * 2; ++q) acc[q] = 0.f;

  if (deg <= 64) {
    // ---- fused register path ----
    int s0 = 0, s1 = 0;
    float e0 = -1e30f, e1 = -1e30f;
    if (lane < deg) {
      s0 = g_srcs[beg + lane];
      float e = als[s0] + aldn;
      e0 = (e > 0.f) ? e : 0.2f * e;
    }
    if (32 + lane < deg) {
      s1 = g_srcs[beg + 32 + lane];
      float e = als[s1] + aldn;
      e1 = (e > 0.f) ? e : 0.2f * e;
    }
    float mx = fmaxf(e0, e1);
#pragma unroll
    for (int o = 16; o; o >>= 1)
      mx = fmaxf(mx, __shfl_xor_sync(0xffffffffu, mx, o));
    float ex0 = (lane < deg) ? __expf(e0 - mx) : 0.f;
    float ex1 = (32 + lane < deg) ? __expf(e1 - mx) : 0.f;
    float sum = ex0 + ex1;
#pragma unroll
    for (int o = 16; o; o >>= 1)
      sum += __shfl_xor_sync(0xffffffffu, sum, o);
    float inv = 1.f / sum;

    int jj = 0;
    for (; jj + 2 <= deg; jj += 2) {
      int   ls0 = __shfl_sync(0xffffffffu, (jj < 32) ? s0 : s1, jj & 31);
      float le0 = __shfl_sync(0xffffffffu, (jj < 32) ? ex0 : ex1, jj & 31);
      int   ls1 = __shfl_sync(0xffffffffu, (jj + 1 < 32) ? s0 : s1, (jj + 1) & 31);
      float le1 = __shfl_sync(0xffffffffu, (jj + 1 < 32) ? ex0 : ex1, (jj + 1) & 31);
      float al0 = le0 * inv, al1 = le1 * inv;
      unsigned w0[NW], w1[NW];
      if (NW == 4) {
        uint4 u0 = __ldg((const uint4*)(h + (size_t)ls0 * Mw) + lane);
        uint4 u1 = __ldg((const uint4*)(h + (size_t)ls1 * Mw) + lane);
        w0[0] = u0.x; w0[1] = u0.y; w0[2] = u0.z; w0[3] = u0.w;
        w1[0] = u1.x; w1[1] = u1.y; w1[2] = u1.z; w1[3] = u1.w;
      } else {
        uint2 u0 = __ldg((const uint2*)(h + (size_t)ls0 * Mw) + lane);
        uint2 u1 = __ldg((const uint2*)(h + (size_t)ls1 * Mw) + lane);
        w0[0] = u0.x; w0[1] = u0.y;
        w1[0] = u1.x; w1[1] = u1.y;
      }
#pragma unroll
      for (int q = 0; q < NW; ++q) {
        acc[2 * q + 0] = fmaf(al0, blo(w0[q]), fmaf(al1, blo(w1[q]), acc[2 * q + 0]));
        acc[2 * q + 1] = fmaf(al0, bhi(w0[q]), fmaf(al1, bhi(w1[q]), acc[2 * q + 1]));
      }
    }
    if (jj < deg) {
      int   ls0 = __shfl_sync(0xffffffffu, (jj < 32) ? s0 : s1, jj & 31);
      float le0 = __shfl_sync(0xffffffffu, (jj < 32) ? ex0 : ex1, jj & 31);
      float al0 = le0 * inv;
      unsigned w0[NW];
      if (NW == 4) {
        uint4 u0 = __ldg((const uint4*)(h + (size_t)ls0 * Mw) + lane);
        w0[0] = u0.x; w0[1] = u0.y; w0[2] = u0.z; w0[3] = u0.w;
      } else {
        uint2 u0 = __ldg((const uint2*)(h + (size_t)ls0 * Mw) + lane);
        w0[0] = u0.x; w0[1] = u0.y;
      }
#pragma unroll
      for (int q = 0; q < NW; ++q) {
        acc[2 * q + 0] = fmaf(al0, blo(w0[q]), acc[2 * q + 0]);
        acc[2 * q + 1] = fmaf(al0, bhi(w0[q]), acc[2 * q + 1]);
      }
    }
  } else {
    // ---- fallback: global scratch (rare / impossible for this dataset) ----
    float mx = -1e30f;
    for (int j = beg + lane; j < end; j += 32) {
      float e = als[g_srcs[j]] + aldn;
      e = (e > 0.f) ? e : 0.2f * e;
      g_escr[j] = e;
      mx = fmaxf(mx, e);
    }
#pragma unroll
    for (int o = 16; o; o >>= 1)
      mx = fmaxf(mx, __shfl_xor_sync(0xffffffffu, mx, o));
    float sum = 0.f;
    for (int j = beg + lane; j < end; j += 32) {
      float ex = __expf(g_escr[j] - mx);
      g_escr[j] = ex;
      sum += ex;
    }
#pragma unroll
    for (int o = 16; o; o >>= 1)
      sum += __shfl_xor_sync(0xffffffffu, sum, o);
    float inv = 1.f / sum;
    __syncwarp();
    for (int j = beg; j < end; ++j) {
      float al = g_escr[j] * inv;
      unsigned w0[NW];
      if (NW == 4) {
        uint4 u0 = __ldg((const uint4*)(h + (size_t)g_srcs[j] * Mw) + lane);
        w0[0] = u0.x; w0[1] = u0.y; w0[2] = u0.z; w0[3] = u0.w;
      } else {
        uint2 u0 = __ldg((const uint2*)(h + (size_t)g_srcs[j] * Mw) + lane);
        w0[0] = u0.x; w0[1] = u0.y;
      }
#pragma unroll
      for (int q = 0; q < NW; ++q) {
        acc[2 * q + 0] = fmaf(al, blo(w0[q]), acc[2 * q + 0]);
        acc[2 * q + 1] = fmaf(al, bhi(w0[q]), acc[2 * q + 1]);
      }
    }
  }

  // lane covers columns [lane*2*NW, lane*2*NW + 2*NW)
  float* orow = out + (size_t)node * M + lane * 2 * NW;
  const float* brow = bias + lane * 2 * NW;
#pragma unroll
  for (int q = 0; q < 2 * NW; q += 4) {
    float4 b = *(const float4*)(brow + q);
    float4 r = make_float4(acc[q] + b.x, acc[q + 1] + b.y,
                           acc[q + 2] + b.z, acc[q + 3] + b.w);
    if (RELU) {
      r.x = fmaxf(r.x, 0.f); r.y = fmaxf(r.y, 0.f);
      r.z = fmaxf(r.z, 0.f); r.w = fmaxf(r.w, 0.f);
    }
    *(float4*)(orow + q) = r;
  }
}

// ---------------- host driver ----------------
extern "C" void kernel_launch(void* const* d_in, const int* in_sizes, int n_in,
                              void* d_out, int out_size) {
  const float* x = (const float*)d_in[0];
  const void* eidx = d_in[1];
  const int base = n_in - 12;
  const float* W1  = (const float*)d_in[base + 0];
  const float* as1 = (const float*)d_in[base + 1];
  const float* ad1 = (const float*)d_in[base + 2];
  const float* b1  = (const float*)d_in[base + 3];
  const float* W2  = (const float*)d_in[base + 4];
  const float* as2 = (const float*)d_in[base + 5];
  const float* ad2 = (const float*)d_in[base + 6];
  const float* b2  = (const float*)d_in[base + 7];
  const float* W3  = (const float*)d_in[base + 8];
  const float* as3 = (const float*)d_in[base + 9];
  const float* ad3 = (const float*)d_in[base + 10];
  const float* b3  = (const float*)d_in[base + 11];

  const int N = in_sizes[0] / 128;
  const int E = in_sizes[1] / 2;

  unsigned* bufA;
  float* bufB;
  float *alsA, *aldA, *alsB, *aldB, *alsC, *aldC;
  cudaGetSymbolAddress((void**)&bufA, g_bufA);
  cudaGetSymbolAddress((void**)&bufB, g_bufB);
  cudaGetSymbolAddress((void**)&alsA, g_alsA);
  cudaGetSymbolAddress((void**)&aldA, g_aldA);
  cudaGetSymbolAddress((void**)&alsB, g_alsB);
  cudaGetSymbolAddress((void**)&aldB, g_aldB);
  cudaGetSymbolAddress((void**)&alsC, g_alsC);
  cudaGetSymbolAddress((void**)&aldC, g_aldC);

  // CSR build (once — shared by all 3 layers) + zero dot accumulators
  init_kernel<<<160, 256>>>(eidx);
  hist_kernel<<<(E + 255) / 256, 256>>>(eidx, E);
  scan_kernel<<<1, 1024>>>(N);
  scatter_kernel<<<(E + N + 255) / 256, 256>>>(eidx, E, N);

  const int gy = (N + 127) / 128;
  const int agg_blocks = (N + 7) / 8;

  // Layer 1: x[N,128] -> h1(bf16)[N,256] (relu after agg)
  gemm_tc_kernel<<<dim3(2, gy), 256>>>(x, W1, bufA, as1, ad1, alsA, aldA, N, 128, 256);
  attn_agg_kernel<256, true><<<agg_blocks, 256>>>(bufA, b1, bufB, alsA, aldA, N);

  // Layer 2: h1agg[N,256] -> h2(bf16)[N,256]
  gemm_tc_kernel<<<dim3(2, gy), 256>>>(bufB, W2, bufA, as2, ad2, alsB, aldB, N, 256, 256);
  attn_agg_kernel<256, true><<<agg_blocks, 256>>>(bufA, b2, bufB, alsB, aldB, N);

  // Layer 3: h2agg[N,256] -> h3(bf16)[N,128] -> out fp32
  gemm_tc_kernel<<<dim3(1, gy), 256>>>(bufB, W3, bufA, as3, ad3, alsC, aldC, N, 256, 128);
  attn_agg_kernel<128, false><<<agg_blocks, 256>>>(bufA, b3, (float*)d_out, alsC, aldC, N);
}